// round 8
// baseline (speedup 1.0000x reference)
#include <cuda_runtime.h>
#include <cuda_bf16.h>
#include <cstdint>
#include <cstddef>

#define SEQ 2048
#define DIM 1024
#define NH 16
#define HD 64
#define ROWS 16
#define COLT 256
#define LCAP 256   // max compacted support entries per row (overflow -> dense fallback)

// Scratch (allocation-free rule: __device__ globals)
__device__ float g_Q[SEQ * DIM];
__device__ float g_K[SEQ * DIM];
__device__ float g_V[SEQ * DIM];
__device__ float g_AO[SEQ * DIM];

__device__ __nv_bfloat16 g_xh[SEQ * DIM], g_xm[SEQ * DIM];
__device__ __nv_bfloat16 g_aoh[SEQ * DIM], g_aom[SEQ * DIM];
__device__ __nv_bfloat16 g_wvh[DIM * DIM], g_wvm[DIM * DIM];
__device__ __nv_bfloat16 g_woh[DIM * DIM], g_wom[DIM * DIM];

// ===========================================================================
// Helpers
// ===========================================================================
__device__ __forceinline__ uint32_t smem_u32(const void* p) {
    uint32_t a;
    asm("{ .reg .u64 t; cvta.to.shared.u64 t, %1; cvt.u32.u64 %0, t; }"
        : "=r"(a) : "l"(p));
    return a;
}
__device__ __forceinline__ void ldsm4(uint32_t* r, uint32_t addr) {
    asm volatile("ldmatrix.sync.aligned.m8n8.x4.shared.b16 {%0,%1,%2,%3}, [%4];"
                 : "=r"(r[0]), "=r"(r[1]), "=r"(r[2]), "=r"(r[3]) : "r"(addr));
}
__device__ __forceinline__ void mma16816(float* c, const uint32_t* a, const uint32_t* b) {
    asm volatile(
        "mma.sync.aligned.m16n8k16.row.col.f32.bf16.bf16.f32 "
        "{%0,%1,%2,%3}, {%4,%5,%6,%7}, {%8,%9}, {%0,%1,%2,%3};"
        : "+f"(c[0]), "+f"(c[1]), "+f"(c[2]), "+f"(c[3])
        : "r"(a[0]), "r"(a[1]), "r"(a[2]), "r"(a[3]), "r"(b[0]), "r"(b[1]));
}
__device__ __forceinline__ void cp16(uint32_t s, const void* g) {
    asm volatile("cp.async.ca.shared.global [%0], [%1], 16;" :: "r"(s), "l"(g));
}

// ===========================================================================
// Split fp32 -> 2x bf16 (h + m captures ~16 mantissa bits)
// ===========================================================================
__global__ __launch_bounds__(256) void split2(
    const float* __restrict__ in, __nv_bfloat16* __restrict__ h,
    __nv_bfloat16* __restrict__ m, int n4)
{
    int i = blockIdx.x * 256 + threadIdx.x;
    if (i >= n4) return;
    float4 v = ((const float4*)in)[i];
    float f[4] = {v.x, v.y, v.z, v.w};
    __nv_bfloat16 hh[4], mm[4];
#pragma unroll
    for (int j = 0; j < 4; j++) {
        hh[j] = __float2bfloat16_rn(f[j]);
        mm[j] = __float2bfloat16_rn(f[j] - __bfloat162float(hh[j]));
    }
    ((__nv_bfloat162*)h)[i * 2 + 0] = __nv_bfloat162(hh[0], hh[1]);
    ((__nv_bfloat162*)h)[i * 2 + 1] = __nv_bfloat162(hh[2], hh[3]);
    ((__nv_bfloat162*)m)[i * 2 + 0] = __nv_bfloat162(mm[0], mm[1]);
    ((__nv_bfloat162*)m)[i * 2 + 1] = __nv_bfloat162(mm[2], mm[3]);
}

// ===========================================================================
// fp32 SIMT SGEMM (fp32-faithful; feeds the entmax-sensitive score path)
// C[M,N] = A[M,K]*B[N,K]^T. blockIdx.z selects among up to 3 (B,C) pairs.
// ===========================================================================
__global__ __launch_bounds__(256, 2) void sgemm_nt3(
    const float* __restrict__ A,
    const float* __restrict__ B0, const float* __restrict__ B1, const float* __restrict__ B2,
    float* __restrict__ C0, float* __restrict__ C1, float* __restrict__ C2,
    int Kdim, int Ndim)
{
    const float* B = (blockIdx.z == 0) ? B0 : ((blockIdx.z == 1) ? B1 : B2);
    float* C = (blockIdx.z == 0) ? C0 : ((blockIdx.z == 1) ? C1 : C2);

    __shared__ __align__(16) float As[8][128];
    __shared__ __align__(16) float Bs[8][128];

    const int tid = threadIdx.x;
    const int m0 = blockIdx.y * 128;
    const int n0 = blockIdx.x * 128;
    const float* Ab = A + (size_t)m0 * Kdim;
    const float* Bb = B + (size_t)n0 * Kdim;

    const int lr = tid >> 1;
    const int lk = (tid & 1) * 4;

    const int warp = tid >> 5, lane = tid & 31;
    const int tr = (warp & 3) * 32 + (lane & 3) * 8;
    const int tc = (warp >> 2) * 64 + (lane >> 2) * 8;

    float acc[8][8];
#pragma unroll
    for (int i = 0; i < 8; i++)
#pragma unroll
        for (int j = 0; j < 8; j++) acc[i][j] = 0.f;

    for (int k0 = 0; k0 < Kdim; k0 += 8) {
        float4 a4 = *(const float4*)(Ab + (size_t)lr * Kdim + k0 + lk);
        float4 b4 = *(const float4*)(Bb + (size_t)lr * Kdim + k0 + lk);
        As[lk + 0][lr] = a4.x; As[lk + 1][lr] = a4.y;
        As[lk + 2][lr] = a4.z; As[lk + 3][lr] = a4.w;
        Bs[lk + 0][lr] = b4.x; Bs[lk + 1][lr] = b4.y;
        Bs[lk + 2][lr] = b4.z; Bs[lk + 3][lr] = b4.w;
        __syncthreads();
#pragma unroll
        for (int kk = 0; kk < 8; kk++) {
            float ar[8], br[8];
            *(float4*)(ar)     = *(const float4*)&As[kk][tr];
            *(float4*)(ar + 4) = *(const float4*)&As[kk][tr + 4];
            *(float4*)(br)     = *(const float4*)&Bs[kk][tc];
            *(float4*)(br + 4) = *(const float4*)&Bs[kk][tc + 4];
#pragma unroll
            for (int i = 0; i < 8; i++)
#pragma unroll
                for (int j = 0; j < 8; j++) acc[i][j] += ar[i] * br[j];
        }
        __syncthreads();
    }

#pragma unroll
    for (int i = 0; i < 8; i++) {
        float* crow = C + (size_t)(m0 + tr + i) * Ndim + n0 + tc;
        *(float4*)(crow)     = make_float4(acc[i][0], acc[i][1], acc[i][2], acc[i][3]);
        *(float4*)(crow + 4) = make_float4(acc[i][4], acc[i][5], acc[i][6], acc[i][7]);
    }
}

// ===========================================================================
// bf16 3-term tensor-core GEMM: C = Ah*Bh + Am*Bh + Ah*Bm  (~2^-18 element)
// For entmax-insensitive paths only (V projection, Wo projection).
// ===========================================================================
#define GPITCH 80
#define GTILE  (128 * GPITCH)
#define GSTAGE (4 * GTILE)
#define GSMEM  (3 * GSTAGE)
#define S_AH 0
#define S_AM 1
#define S_BH 2
#define S_BM 3

__global__ __launch_bounds__(256) void gemm_bf3(
    const __nv_bfloat16* __restrict__ Ah, const __nv_bfloat16* __restrict__ Am,
    const __nv_bfloat16* __restrict__ Bh, const __nv_bfloat16* __restrict__ Bm,
    float* __restrict__ C, int Kdim, int Ndim)
{
    extern __shared__ __align__(16) char smem[];

    const int tid = threadIdx.x;
    const int lane = tid & 31, warp = tid >> 5;
    const int m0 = blockIdx.y * 128;
    const int n0 = blockIdx.x * 128;
    const int wm = (warp >> 2) * 64;
    const int wn = (warp & 3) * 32;
    const int lr = tid >> 2;
    const int lq = tid & 3;

    const uint32_t sb = smem_u32(smem);
    const uint32_t aBase = sb + (uint32_t)(wm + (lane & 15)) * GPITCH + (lane >> 4) * 16;
    const uint32_t bBase = sb + (uint32_t)(wn + ((lane >> 4) << 3) + (lane & 7)) * GPITCH
                              + ((lane >> 3) & 1) * 16;

    float acc[4][4][4];
#pragma unroll
    for (int a = 0; a < 4; a++)
#pragma unroll
        for (int b = 0; b < 4; b++)
#pragma unroll
            for (int k = 0; k < 4; k++) acc[a][b][k] = 0.f;

    const int NC = Kdim >> 5;

#define ISSUE_SUB(G, row0, sub, st, k0)                                         \
    {                                                                           \
        _Pragma("unroll")                                                       \
        for (int it = 0; it < 2; it++) {                                        \
            int r = lr + it * 64;                                               \
            cp16(sb + (st) * GSTAGE + (sub) * GTILE + r * GPITCH + lq * 16,     \
                 (const char*)(G) + ((size_t)((row0) + r) * Kdim + (k0)) * 2 + lq * 16); \
        }                                                                       \
    }
#define ISSUE(ch, st)                                                           \
    {                                                                           \
        const int k0_ = (ch) * 32;                                              \
        ISSUE_SUB(Ah, m0, S_AH, st, k0_);                                       \
        ISSUE_SUB(Am, m0, S_AM, st, k0_);                                       \
        ISSUE_SUB(Bh, n0, S_BH, st, k0_);                                       \
        ISSUE_SUB(Bm, n0, S_BM, st, k0_);                                       \
        asm volatile("cp.async.commit_group;");                                 \
    }

    ISSUE(0, 0);
    ISSUE(1, 1);

    for (int c = 0; c < NC; c++) {
        const int st = c % 3;
        if (c + 1 < NC) asm volatile("cp.async.wait_group 1;");
        else            asm volatile("cp.async.wait_group 0;");
        __syncthreads();
        if (c + 2 < NC) ISSUE(c + 2, (c + 2) % 3);

        const uint32_t sah = aBase + st * GSTAGE;
        const uint32_t sbh = bBase + st * GSTAGE + S_BH * GTILE;
#pragma unroll
        for (int ks = 0; ks < 2; ks++) {
            const uint32_t ko = ks * 32;
            uint32_t ah[4][4], am[4], bh[8], bm[8];
#pragma unroll
            for (int mb = 0; mb < 4; mb++)
                ldsm4(ah[mb], sah + S_AH * GTILE + mb * (16 * GPITCH) + ko);
            ldsm4(bh,     sbh + ko);
            ldsm4(bh + 4, sbh + 16 * GPITCH + ko);
#pragma unroll
            for (int mb = 0; mb < 4; mb++)
#pragma unroll
                for (int nb = 0; nb < 4; nb++)
                    mma16816(acc[mb][nb], ah[mb], &bh[nb * 2]);      // h*h
            ldsm4(bm,     sbh + (S_BM - S_BH) * GTILE + ko);
            ldsm4(bm + 4, sbh + (S_BM - S_BH) * GTILE + 16 * GPITCH + ko);
#pragma unroll
            for (int mb = 0; mb < 4; mb++)
#pragma unroll
                for (int nb = 0; nb < 4; nb++)
                    mma16816(acc[mb][nb], ah[mb], &bm[nb * 2]);      // h*m
#pragma unroll
            for (int mb = 0; mb < 4; mb++) {
                ldsm4(am, sah + S_AM * GTILE + mb * (16 * GPITCH) + ko);
#pragma unroll
                for (int nb = 0; nb < 4; nb++)
                    mma16816(acc[mb][nb], am, &bh[nb * 2]);          // m*h
            }
        }
    }

    const int g = lane >> 2, t = lane & 3;
#pragma unroll
    for (int mb = 0; mb < 4; mb++) {
#pragma unroll
        for (int nb = 0; nb < 4; nb++) {
            float* p0 = C + (size_t)(m0 + wm + mb * 16 + g) * Ndim + n0 + wn + nb * 8 + t * 2;
            float* p1 = p0 + 8 * Ndim;
            *(float2*)p0 = make_float2(acc[mb][nb][0], acc[mb][nb][1]);
            *(float2*)p1 = make_float2(acc[mb][nb][2], acc[mb][nb][3]);
        }
    }
#undef ISSUE
#undef ISSUE_SUB
}

// ---------------------------------------------------------------------------
// Fused causal entmax attention with SPARSE PV.
// Phase 2 (scores): unchanged fp32 register-blocked (feeds entmax -> faithful).
// Phase 3+4 fused per row (1 warp per row): Michelot support -> tau*, then one
// scan computes p=relu(s-tau*), psum, and compacts support (ballot+popc) into
// a per-row smem list; sparse PV walks the list (unrolled x4, coalesced V row
// reads from global), scales by 1/psum at the end. Overflow (>LCAP) falls back
// to a dense per-row loop (correct, slow, statistically never taken).
// ---------------------------------------------------------------------------
__global__ __launch_bounds__(256) void attn_kernel(
    const float* __restrict__ Q, const float* __restrict__ K,
    const float* __restrict__ V, float* __restrict__ O)
{
    extern __shared__ float sm[];
    float* sc = sm;                        // ROWS * SEQ fp32 scores
    float* qs = sm + ROWS * SEQ;           // ROWS * HD
    float* kv = qs + ROWS * HD;            // 16384 floats: K tiles, then lists
    float4* kt4 = (float4*)kv;
    float2* lists = (float2*)kv;           // [ROWS][LCAP] (j-as-int, p)

    const int tid = threadIdx.x;
    const int h = blockIdx.y;
    const int r0 = blockIdx.x * ROWS;
    const int n_max = r0 + ROWS;
    const int ntiles = (n_max + COLT - 1) / COLT;

    // ---- Phase 1: q rows (scale folded in) ----
    for (int i = tid; i < ROWS * HD; i += 256) {
        int r = i >> 6, d = i & 63;
        qs[r * 64 + d] = Q[(size_t)(r0 + r) * DIM + h * HD + d] * 0.125f;
    }

    // ---- Phase 2: scores (fp32, register-blocked) ----
    {
        const int cg = tid & 63;
        const int rg = tid >> 6;
        const int cs = cg & 15;

        for (int t = 0; t < ntiles; t++) {
            const int c0 = t * COLT;
            __syncthreads();
            {
                const float4* Kg = (const float4*)(K + (size_t)c0 * DIM + h * HD);
#pragma unroll
                for (int it = 0; it < 16; it++) {
                    int i = it * 256 + tid;
                    int c = i >> 4, dq = i & 15;
                    kt4[c * 16 + (dq ^ ((c >> 2) & 15))] = Kg[(size_t)c * 256 + dq];
                }
            }
            __syncthreads();

            float acc[4][4];
#pragma unroll
            for (int i = 0; i < 4; i++)
#pragma unroll
                for (int j = 0; j < 4; j++) acc[i][j] = 0.f;

#pragma unroll
            for (int dq = 0; dq < 16; dq++) {
                float4 q0 = *(const float4*)&qs[(rg * 4 + 0) * 64 + dq * 4];
                float4 q1 = *(const float4*)&qs[(rg * 4 + 1) * 64 + dq * 4];
                float4 q2 = *(const float4*)&qs[(rg * 4 + 2) * 64 + dq * 4];
                float4 q3 = *(const float4*)&qs[(rg * 4 + 3) * 64 + dq * 4];
                float4 k0 = kt4[(cg * 4 + 0) * 16 + (dq ^ cs)];
                float4 k1 = kt4[(cg * 4 + 1) * 16 + (dq ^ cs)];
                float4 k2 = kt4[(cg * 4 + 2) * 16 + (dq ^ cs)];
                float4 k3 = kt4[(cg * 4 + 3) * 16 + (dq ^ cs)];
#define DOT4(a, b) (a.x * b.x + a.y * b.y + a.z * b.z + a.w * b.w)
                acc[0][0] += DOT4(q0, k0); acc[0][1] += DOT4(q0, k1);
                acc[0][2] += DOT4(q0, k2); acc[0][3] += DOT4(q0, k3);
                acc[1][0] += DOT4(q1, k0); acc[1][1] += DOT4(q1, k1);
                acc[1][2] += DOT4(q1, k2); acc[1][3] += DOT4(q1, k3);
                acc[2][0] += DOT4(q2, k0); acc[2][1] += DOT4(q2, k1);
                acc[2][2] += DOT4(q2, k2); acc[2][3] += DOT4(q2, k3);
                acc[3][0] += DOT4(q3, k0); acc[3][1] += DOT4(q3, k1);
                acc[3][2] += DOT4(q3, k2); acc[3][3] += DOT4(q3, k3);
            }
#pragma unroll
            for (int i = 0; i < 4; i++) {
                *(float4*)&sc[(size_t)(rg * 4 + i) * SEQ + c0 + cg * 4] =
                    make_float4(acc[i][0], acc[i][1], acc[i][2], acc[i][3]);
            }
        }
    }
    __syncthreads();   // sc complete; kv (tiles) now free for lists

    // ---- Phase 3+4 fused: entmax + sparse PV, one warp per row ----
    {
        const int w = tid >> 5, lane = tid & 31;
        const float* Vh = V + h * HD + 2 * lane;   // per-lane dim pair base

        for (int rr = w; rr < ROWS; rr += 8) {
            const int n = r0 + rr + 1;
            float* srow = sc + (size_t)rr * SEQ;

            // total sum
            float ssum = 0.f;
            for (int j = lane; j < n; j += 32) ssum += srow[j];
#pragma unroll
            for (int o = 16; o; o >>= 1) ssum += __shfl_xor_sync(0xFFFFFFFFu, ssum, o);

            // Michelot fixed point -> support size k
            int k = n;
            float tau = (ssum - 1.0f) / (float)n;
            for (int it = 0; it < SEQ; ++it) {
                float sa = 0.f; int ca = 0;
                for (int j = lane; j < n; j += 32) {
                    float v = srow[j];
                    if (v > tau) { sa += v; ca++; }
                }
#pragma unroll
                for (int o = 16; o; o >>= 1) {
                    sa += __shfl_xor_sync(0xFFFFFFFFu, sa, o);
                    ca += __shfl_xor_sync(0xFFFFFFFFu, ca, o);
                }
                if (ca == k) break;
                k = ca;
                tau = (sa - 1.0f) / (float)ca;
            }

            const float tau_star = (ssum - 1.0f) / (float)k;  // reference quirk: TOTAL sum

            // pass A: psum + support compaction
            float2* list = lists + (size_t)rr * LCAP;
            float psum = 0.f;
            int count = 0;
            bool ovf = false;
            for (int j0 = 0; j0 < n; j0 += 32) {
                int j = j0 + lane;
                float p = 0.f;
                if (j < n) p = fmaxf(srow[j] - tau_star, 0.f);
                psum += p;
                unsigned mask = __ballot_sync(0xFFFFFFFFu, p > 0.f);
                int cnt = __popc(mask);
                if (count + cnt <= LCAP) {
                    if (p > 0.f) {
                        int idx = count + __popc(mask & ((1u << lane) - 1u));
                        list[idx] = make_float2(__int_as_float(j), p);
                    }
                }
                else ovf = true;
                count += cnt;
            }
#pragma unroll
            for (int o = 16; o; o >>= 1) psum += __shfl_xor_sync(0xFFFFFFFFu, psum, o);
            const float inv = 1.0f / (psum + 1e-10f);

            // pass B: sparse PV (each lane owns dims 2*lane, 2*lane+1)
            float o0 = 0.f, o1 = 0.f;
            if (!ovf) {
                int i = 0;
                for (; i + 4 <= count; i += 4) {
                    float2 e0 = list[i],     e1 = list[i + 1];
                    float2 e2 = list[i + 2], e3 = list[i + 3];
                    float2 v0 = *(const float2*)(Vh + (size_t)__float_as_int(e0.x) * DIM);
                    float2 v1 = *(const float2*)(Vh + (size_t)__float_as_int(e1.x) * DIM);
                    float2 v2 = *(const float2*)(Vh + (size_t)__float_as_int(e2.x) * DIM);
                    float2 v3 = *(const float2*)(Vh + (size_t)__float_as_int(e3.x) * DIM);
                    o0 += e0.y * v0.x; o1 += e0.y * v0.y;
                    o0 += e1.y * v1.x; o1 += e1.y * v1.y;
                    o0 += e2.y * v2.x; o1 += e2.y * v2.y;
                    o0 += e3.y * v3.x; o1 += e3.y * v3.y;
                }
                for (; i < count; i++) {
                    float2 e = list[i];
                    float2 v = *(const float2*)(Vh + (size_t)__float_as_int(e.x) * DIM);
                    o0 += e.y * v.x; o1 += e.y * v.y;
                }
            } else {
                // dense fallback (support exceeded LCAP)
                for (int j = 0; j < n; j++) {
                    float p = fmaxf(srow[j] - tau_star, 0.f);
                    if (p > 0.f) {
                        float2 v = *(const float2*)(Vh + (size_t)j * DIM);
                        o0 += p * v.x; o1 += p * v.y;
                    }
                }
            }
            *(float2*)&O[(size_t)(r0 + rr) * DIM + h * HD + 2 * lane] =
                make_float2(o0 * inv, o1 * inv);
        }
    }
}

// ---------------------------------------------------------------------------
extern "C" void kernel_launch(void* const* d_in, const int* in_sizes, int n_in,
                              void* d_out, int out_size)
{
    const float* x  = (const float*)d_in[0];
    const float* Wq = (const float*)d_in[1];
    const float* Wk = (const float*)d_in[2];
    const float* Wv = (const float*)d_in[3];
    const float* Wo = (const float*)d_in[4];
    float* out = (float*)d_out;

    float *Qp, *Kp, *Vp, *AOp;
    cudaGetSymbolAddress((void**)&Qp,  g_Q);
    cudaGetSymbolAddress((void**)&Kp,  g_K);
    cudaGetSymbolAddress((void**)&Vp,  g_V);
    cudaGetSymbolAddress((void**)&AOp, g_AO);

    __nv_bfloat16 *xh, *xm, *aoh, *aom, *wvh, *wvm, *woh, *wom;
    cudaGetSymbolAddress((void**)&xh,  g_xh);  cudaGetSymbolAddress((void**)&xm,  g_xm);
    cudaGetSymbolAddress((void**)&aoh, g_aoh); cudaGetSymbolAddress((void**)&aom, g_aom);
    cudaGetSymbolAddress((void**)&wvh, g_wvh); cudaGetSymbolAddress((void**)&wvm, g_wvm);
    cudaGetSymbolAddress((void**)&woh, g_woh); cudaGetSymbolAddress((void**)&wom, g_wom);

    const size_t attn_smem = (ROWS * SEQ + ROWS * HD + 16384) * sizeof(float);
    cudaFuncSetAttribute(attn_kernel, cudaFuncAttributeMaxDynamicSharedMemorySize,
                         (int)attn_smem);
    cudaFuncSetAttribute(gemm_bf3, cudaFuncAttributeMaxDynamicSharedMemorySize, GSMEM);

    const int n4x = SEQ * DIM / 4;
    const int n4w = DIM * DIM / 4;

    // splits (flip-insensitive operands only)
    split2<<<n4x / 256, 256>>>(x,  xh,  xm,  n4x);
    split2<<<n4w / 256, 256>>>(Wv, wvh, wvm, n4w);
    split2<<<n4w / 256, 256>>>(Wo, woh, wom, n4w);

    {   // Q,K projections: fp32-faithful (entmax support is flip-sensitive)
        dim3 grid(DIM / 128, SEQ / 128, 2);
        sgemm_nt3<<<grid, 256>>>(x, Wq, Wk, Wk, Qp, Kp, Kp, DIM, DIM);
    }
    {   // V projection: bf16x3 tensor cores (errors pass linearly to output)
        dim3 grid(DIM / 128, SEQ / 128, 1);
        gemm_bf3<<<grid, 256, GSMEM>>>(xh, xm, wvh, wvm, Vp, DIM, DIM);
    }
    {   // fused entmax attention (sparse PV)
        dim3 grid(SEQ / ROWS, NH);
        attn_kernel<<<grid, 256, attn_smem>>>(Qp, Kp, Vp, AOp);
    }
    split2<<<n4x / 256, 256>>>(AOp, aoh, aom, n4x);
    {   // output projection: bf16x3 tensor cores (post-entmax, flip-free)
        dim3 grid(DIM / 128, SEQ / 128, 1);
        gemm_bf3<<<grid, 256, GSMEM>>>(aoh, aom, woh, wom, out, DIM, DIM);
    }
}

// round 9
// speedup vs baseline: 1.3502x; 1.3502x over previous
#include <cuda_runtime.h>
#include <cuda_bf16.h>
#include <cstdint>
#include <cstddef>

#define SEQ 2048
#define DIM 1024
#define NH 16
#define HD 64
#define ROWS 16
#define COLT 256

typedef unsigned long long u64;

// Scratch (allocation-free rule: __device__ globals)
__device__ float g_Q[SEQ * DIM];
__device__ float g_K[SEQ * DIM];
__device__ float g_V[SEQ * DIM];

__device__ __nv_bfloat16 g_xh[SEQ * DIM], g_xm[SEQ * DIM];
__device__ __nv_bfloat16 g_aoh[SEQ * DIM], g_aom[SEQ * DIM];
__device__ __nv_bfloat16 g_wvh[DIM * DIM], g_wvm[DIM * DIM];
__device__ __nv_bfloat16 g_woh[DIM * DIM], g_wom[DIM * DIM];

// ===========================================================================
// Helpers
// ===========================================================================
__device__ __forceinline__ uint32_t smem_u32(const void* p) {
    uint32_t a;
    asm("{ .reg .u64 t; cvta.to.shared.u64 t, %1; cvt.u32.u64 %0, t; }"
        : "=r"(a) : "l"(p));
    return a;
}
__device__ __forceinline__ u64 pk2(float lo, float hi) {
    u64 r;
    asm("mov.b64 %0, {%1, %2};" : "=l"(r) : "f"(lo), "f"(hi));
    return r;
}
__device__ __forceinline__ float2 upk(u64 v) {
    float lo, hi;
    asm("mov.b64 {%0, %1}, %2;" : "=f"(lo), "=f"(hi) : "l"(v));
    return make_float2(lo, hi);
}
__device__ __forceinline__ u64 ffma2(u64 a, u64 b, u64 c) {
    u64 d;
    asm("fma.rn.f32x2 %0, %1, %2, %3;" : "=l"(d) : "l"(a), "l"(b), "l"(c));
    return d;
}
__device__ __forceinline__ void lds2u64(u64& a, u64& b, uint32_t addr) {
    asm volatile("ld.shared.v2.u64 {%0, %1}, [%2];" : "=l"(a), "=l"(b) : "r"(addr));
}
__device__ __forceinline__ void ldsm4(uint32_t* r, uint32_t addr) {
    asm volatile("ldmatrix.sync.aligned.m8n8.x4.shared.b16 {%0,%1,%2,%3}, [%4];"
                 : "=r"(r[0]), "=r"(r[1]), "=r"(r[2]), "=r"(r[3]) : "r"(addr));
}
__device__ __forceinline__ void mma16816(float* c, const uint32_t* a, const uint32_t* b) {
    asm volatile(
        "mma.sync.aligned.m16n8k16.row.col.f32.bf16.bf16.f32 "
        "{%0,%1,%2,%3}, {%4,%5,%6,%7}, {%8,%9}, {%0,%1,%2,%3};"
        : "+f"(c[0]), "+f"(c[1]), "+f"(c[2]), "+f"(c[3])
        : "r"(a[0]), "r"(a[1]), "r"(a[2]), "r"(a[3]), "r"(b[0]), "r"(b[1]));
}
__device__ __forceinline__ void cp16(uint32_t s, const void* g) {
    asm volatile("cp.async.ca.shared.global [%0], [%1], 16;" :: "r"(s), "l"(g));
}

// ===========================================================================
// Split fp32 -> 2x bf16 (h + m captures ~16 mantissa bits)
// ===========================================================================
__global__ __launch_bounds__(256) void split2(
    const float* __restrict__ in, __nv_bfloat16* __restrict__ h,
    __nv_bfloat16* __restrict__ m, int n4)
{
    int i = blockIdx.x * 256 + threadIdx.x;
    if (i >= n4) return;
    float4 v = ((const float4*)in)[i];
    float f[4] = {v.x, v.y, v.z, v.w};
    __nv_bfloat16 hh[4], mm[4];
#pragma unroll
    for (int j = 0; j < 4; j++) {
        hh[j] = __float2bfloat16_rn(f[j]);
        mm[j] = __float2bfloat16_rn(f[j] - __bfloat162float(hh[j]));
    }
    ((__nv_bfloat162*)h)[i * 2 + 0] = __nv_bfloat162(hh[0], hh[1]);
    ((__nv_bfloat162*)h)[i * 2 + 1] = __nv_bfloat162(hh[2], hh[3]);
    ((__nv_bfloat162*)m)[i * 2 + 0] = __nv_bfloat162(mm[0], mm[1]);
    ((__nv_bfloat162*)m)[i * 2 + 1] = __nv_bfloat162(mm[2], mm[3]);
}

// ===========================================================================
// fp32 SIMT SGEMM with packed f32x2 FMAs. Per-element accumulation order is
// IDENTICAL to the scalar version (pairs are across rows) -> bitwise-stable
// numerics on the entmax-sensitive Q/K path.
// C[M,N] = A[M,K]*B[N,K]^T. blockIdx.z selects among up to 3 (B,C) pairs.
// ===========================================================================
__global__ __launch_bounds__(256, 2) void sgemm_nt3(
    const float* __restrict__ A,
    const float* __restrict__ B0, const float* __restrict__ B1, const float* __restrict__ B2,
    float* __restrict__ C0, float* __restrict__ C1, float* __restrict__ C2,
    int Kdim, int Ndim)
{
    const float* B = (blockIdx.z == 0) ? B0 : ((blockIdx.z == 1) ? B1 : B2);
    float* C = (blockIdx.z == 0) ? C0 : ((blockIdx.z == 1) ? C1 : C2);

    __shared__ __align__(16) float As[8][128];
    __shared__ __align__(16) float Bs[8][128];

    const int tid = threadIdx.x;
    const int m0 = blockIdx.y * 128;
    const int n0 = blockIdx.x * 128;
    const float* Ab = A + (size_t)m0 * Kdim;
    const float* Bb = B + (size_t)n0 * Kdim;

    const int lr = tid >> 1;
    const int lk = (tid & 1) * 4;

    const int warp = tid >> 5, lane = tid & 31;
    const int tr = (warp & 3) * 32 + (lane & 3) * 8;
    const int tc = (warp >> 2) * 64 + (lane >> 2) * 8;

    const uint32_t sAb = smem_u32(As);

    u64 acc2[4][8];
#pragma unroll
    for (int i = 0; i < 4; i++)
#pragma unroll
        for (int j = 0; j < 8; j++) acc2[i][j] = 0ull;

    for (int k0 = 0; k0 < Kdim; k0 += 8) {
        float4 a4 = *(const float4*)(Ab + (size_t)lr * Kdim + k0 + lk);
        float4 b4 = *(const float4*)(Bb + (size_t)lr * Kdim + k0 + lk);
        As[lk + 0][lr] = a4.x; As[lk + 1][lr] = a4.y;
        As[lk + 2][lr] = a4.z; As[lk + 3][lr] = a4.w;
        Bs[lk + 0][lr] = b4.x; Bs[lk + 1][lr] = b4.y;
        Bs[lk + 2][lr] = b4.z; Bs[lk + 3][lr] = b4.w;
        __syncthreads();
#pragma unroll
        for (int kk = 0; kk < 8; kk++) {
            u64 ar2[4];
            lds2u64(ar2[0], ar2[1], sAb + (uint32_t)(kk * 128 + tr) * 4);
            lds2u64(ar2[2], ar2[3], sAb + (uint32_t)(kk * 128 + tr + 4) * 4);
            float br[8];
            *(float4*)(br)     = *(const float4*)&Bs[kk][tc];
            *(float4*)(br + 4) = *(const float4*)&Bs[kk][tc + 4];
            u64 br2[8];
#pragma unroll
            for (int j = 0; j < 8; j++) br2[j] = pk2(br[j], br[j]);
#pragma unroll
            for (int i = 0; i < 4; i++)
#pragma unroll
                for (int j = 0; j < 8; j++)
                    acc2[i][j] = ffma2(ar2[i], br2[j], acc2[i][j]);
        }
        __syncthreads();
    }

#pragma unroll
    for (int i = 0; i < 4; i++) {
        float r0v[8], r1v[8];
#pragma unroll
        for (int j = 0; j < 8; j++) {
            float2 p = upk(acc2[i][j]);
            r0v[j] = p.x; r1v[j] = p.y;
        }
        float* c0r = C + (size_t)(m0 + tr + 2 * i) * Ndim + n0 + tc;
        float* c1r = c0r + Ndim;
        *(float4*)(c0r)     = make_float4(r0v[0], r0v[1], r0v[2], r0v[3]);
        *(float4*)(c0r + 4) = make_float4(r0v[4], r0v[5], r0v[6], r0v[7]);
        *(float4*)(c1r)     = make_float4(r1v[0], r1v[1], r1v[2], r1v[3]);
        *(float4*)(c1r + 4) = make_float4(r1v[4], r1v[5], r1v[6], r1v[7]);
    }
}

// ===========================================================================
// bf16 3-term tensor-core GEMM: C = Ah*Bh + Am*Bh + Ah*Bm  (~2^-18 element)
// For entmax-insensitive paths only (V projection, Wo projection).
// ===========================================================================
#define GPITCH 80
#define GTILE  (128 * GPITCH)
#define GSTAGE (4 * GTILE)
#define GSMEM  (3 * GSTAGE)
#define S_AH 0
#define S_AM 1
#define S_BH 2
#define S_BM 3

__global__ __launch_bounds__(256) void gemm_bf3(
    const __nv_bfloat16* __restrict__ Ah, const __nv_bfloat16* __restrict__ Am,
    const __nv_bfloat16* __restrict__ Bh, const __nv_bfloat16* __restrict__ Bm,
    float* __restrict__ C, int Kdim, int Ndim)
{
    extern __shared__ __align__(16) char smem[];

    const int tid = threadIdx.x;
    const int lane = tid & 31, warp = tid >> 5;
    const int m0 = blockIdx.y * 128;
    const int n0 = blockIdx.x * 128;
    const int wm = (warp >> 2) * 64;
    const int wn = (warp & 3) * 32;
    const int lr = tid >> 2;
    const int lq = tid & 3;

    const uint32_t sb = smem_u32(smem);
    const uint32_t aBase = sb + (uint32_t)(wm + (lane & 15)) * GPITCH + (lane >> 4) * 16;
    const uint32_t bBase = sb + (uint32_t)(wn + ((lane >> 4) << 3) + (lane & 7)) * GPITCH
                              + ((lane >> 3) & 1) * 16;

    float acc[4][4][4];
#pragma unroll
    for (int a = 0; a < 4; a++)
#pragma unroll
        for (int b = 0; b < 4; b++)
#pragma unroll
            for (int k = 0; k < 4; k++) acc[a][b][k] = 0.f;

    const int NC = Kdim >> 5;

#define ISSUE_SUB(G, row0, sub, st, k0)                                         \
    {                                                                           \
        _Pragma("unroll")                                                       \
        for (int it = 0; it < 2; it++) {                                        \
            int r = lr + it * 64;                                               \
            cp16(sb + (st) * GSTAGE + (sub) * GTILE + r * GPITCH + lq * 16,     \
                 (const char*)(G) + ((size_t)((row0) + r) * Kdim + (k0)) * 2 + lq * 16); \
        }                                                                       \
    }
#define ISSUE(ch, st)                                                           \
    {                                                                           \
        const int k0_ = (ch) * 32;                                              \
        ISSUE_SUB(Ah, m0, S_AH, st, k0_);                                       \
        ISSUE_SUB(Am, m0, S_AM, st, k0_);                                       \
        ISSUE_SUB(Bh, n0, S_BH, st, k0_);                                       \
        ISSUE_SUB(Bm, n0, S_BM, st, k0_);                                       \
        asm volatile("cp.async.commit_group;");                                 \
    }

    ISSUE(0, 0);
    ISSUE(1, 1);

    for (int c = 0; c < NC; c++) {
        const int st = c % 3;
        if (c + 1 < NC) asm volatile("cp.async.wait_group 1;");
        else            asm volatile("cp.async.wait_group 0;");
        __syncthreads();
        if (c + 2 < NC) ISSUE(c + 2, (c + 2) % 3);

        const uint32_t sah = aBase + st * GSTAGE;
        const uint32_t sbh = bBase + st * GSTAGE + S_BH * GTILE;
#pragma unroll
        for (int ks = 0; ks < 2; ks++) {
            const uint32_t ko = ks * 32;
            uint32_t ah[4][4], am[4], bh[8], bm[8];
#pragma unroll
            for (int mb = 0; mb < 4; mb++)
                ldsm4(ah[mb], sah + S_AH * GTILE + mb * (16 * GPITCH) + ko);
            ldsm4(bh,     sbh + ko);
            ldsm4(bh + 4, sbh + 16 * GPITCH + ko);
#pragma unroll
            for (int mb = 0; mb < 4; mb++)
#pragma unroll
                for (int nb = 0; nb < 4; nb++)
                    mma16816(acc[mb][nb], ah[mb], &bh[nb * 2]);      // h*h
            ldsm4(bm,     sbh + (S_BM - S_BH) * GTILE + ko);
            ldsm4(bm + 4, sbh + (S_BM - S_BH) * GTILE + 16 * GPITCH + ko);
#pragma unroll
            for (int mb = 0; mb < 4; mb++)
#pragma unroll
                for (int nb = 0; nb < 4; nb++)
                    mma16816(acc[mb][nb], ah[mb], &bm[nb * 2]);      // h*m
#pragma unroll
            for (int mb = 0; mb < 4; mb++) {
                ldsm4(am, sah + S_AM * GTILE + mb * (16 * GPITCH) + ko);
#pragma unroll
                for (int nb = 0; nb < 4; nb++)
                    mma16816(acc[mb][nb], am, &bh[nb * 2]);          // m*h
            }
        }
    }

    const int g = lane >> 2, t = lane & 3;
#pragma unroll
    for (int mb = 0; mb < 4; mb++) {
#pragma unroll
        for (int nb = 0; nb < 4; nb++) {
            float* p0 = C + (size_t)(m0 + wm + mb * 16 + g) * Ndim + n0 + wn + nb * 8 + t * 2;
            float* p1 = p0 + 8 * Ndim;
            *(float2*)p0 = make_float2(acc[mb][nb][0], acc[mb][nb][1]);
            *(float2*)p1 = make_float2(acc[mb][nb][2], acc[mb][nb][3]);
        }
    }
#undef ISSUE
#undef ISSUE_SUB
}

// ---------------------------------------------------------------------------
// Fused causal entmax attention (R7 dense structure, f32x2 packed FMAs).
// Epilogue writes the bf16 h/m split of the attention output directly.
// ---------------------------------------------------------------------------
__global__ __launch_bounds__(256) void attn_kernel(
    const float* __restrict__ Q, const float* __restrict__ K,
    const float* __restrict__ V,
    __nv_bfloat16* __restrict__ AOh, __nv_bfloat16* __restrict__ AOm)
{
    extern __shared__ float sm[];
    float* sc = sm;                        // ROWS * SEQ
    float* qs = sm + ROWS * SEQ;           // ROWS * HD
    float* kv = qs + ROWS * HD;            // 16384 floats (tile union)
    float4* kt4 = (float4*)kv;
    float4* vt4 = (float4*)kv;
    float* vts = kv;

    const uint32_t scb = smem_u32(sc);
    const uint32_t qsb = smem_u32(qs);
    const uint32_t kvb = smem_u32(kv);

    const int tid = threadIdx.x;
    const int hh = blockIdx.y;             // head
    const int r0 = blockIdx.x * ROWS;
    const int n_max = r0 + ROWS;
    const int ntiles = (n_max + COLT - 1) / COLT;

    // ---- Phase 1: q rows (scale folded in) ----
    for (int i = tid; i < ROWS * HD; i += 256) {
        int r = i >> 6, d = i & 63;
        qs[r * 64 + d] = Q[(size_t)(r0 + r) * DIM + hh * HD + d] * 0.125f;
    }

    // ---- Phase 2: scores (f32x2) ----
    {
        const int cg = tid & 63;
        const int rg = tid >> 6;
        const int cs = cg & 15;

        for (int t = 0; t < ntiles; t++) {
            const int c0 = t * COLT;
            __syncthreads();
            {
                const float4* Kg = (const float4*)(K + (size_t)c0 * DIM + hh * HD);
#pragma unroll
                for (int it = 0; it < 16; it++) {
                    int i = it * 256 + tid;
                    int c = i >> 4, dq = i & 15;
                    kt4[c * 16 + (dq ^ ((c >> 2) & 15))] = Kg[(size_t)c * 256 + dq];
                }
            }
            __syncthreads();

            u64 acc2[4][4];
#pragma unroll
            for (int i = 0; i < 4; i++)
#pragma unroll
                for (int j = 0; j < 4; j++) acc2[i][j] = 0ull;

#pragma unroll
            for (int dq = 0; dq < 16; dq++) {
                u64 ql[4], qh[4], kl[4], kh[4];
#pragma unroll
                for (int i = 0; i < 4; i++)
                    lds2u64(ql[i], qh[i], qsb + (uint32_t)((rg * 4 + i) * 64 + dq * 4) * 4);
#pragma unroll
                for (int j = 0; j < 4; j++)
                    lds2u64(kl[j], kh[j], kvb + (uint32_t)((cg * 4 + j) * 16 + (dq ^ cs)) * 16);
#pragma unroll
                for (int i = 0; i < 4; i++)
#pragma unroll
                    for (int j = 0; j < 4; j++) {
                        acc2[i][j] = ffma2(ql[i], kl[j], acc2[i][j]);
                        acc2[i][j] = ffma2(qh[i], kh[j], acc2[i][j]);
                    }
            }
#pragma unroll
            for (int i = 0; i < 4; i++) {
                float2 p0 = upk(acc2[i][0]), p1 = upk(acc2[i][1]);
                float2 p2 = upk(acc2[i][2]), p3 = upk(acc2[i][3]);
                *(float4*)&sc[(size_t)(rg * 4 + i) * SEQ + c0 + cg * 4] =
                    make_float4(p0.x + p0.y, p1.x + p1.y, p2.x + p2.y, p3.x + p3.y);
            }
        }
    }
    __syncthreads();

    // ---- Phase 3: entmax per row (one warp per row, 2 rounds) ----
    {
        const int w = tid >> 5, lane = tid & 31;
        const int tile_end = ntiles * COLT;
        for (int rr = w; rr < ROWS; rr += 8) {
            const int n = r0 + rr + 1;
            float* srow = sc + (size_t)rr * SEQ;

            float ssum = 0.f;
            for (int j = lane; j < n; j += 32) ssum += srow[j];
#pragma unroll
            for (int o = 16; o; o >>= 1) ssum += __shfl_xor_sync(0xFFFFFFFFu, ssum, o);

            int k = n;
            float tau = (ssum - 1.0f) / (float)n;
            for (int it = 0; it < SEQ; ++it) {
                float sa = 0.f; int ca = 0;
                for (int j = lane; j < n; j += 32) {
                    float v = srow[j];
                    if (v > tau) { sa += v; ca++; }
                }
#pragma unroll
                for (int o = 16; o; o >>= 1) {
                    sa += __shfl_xor_sync(0xFFFFFFFFu, sa, o);
                    ca += __shfl_xor_sync(0xFFFFFFFFu, ca, o);
                }
                if (ca == k) break;
                k = ca;
                tau = (sa - 1.0f) / (float)ca;
            }

            const float tau_star = (ssum - 1.0f) / (float)k;  // reference quirk: TOTAL sum
            float psum = 0.f;
            for (int j = lane; j < n; j += 32) psum += fmaxf(srow[j] - tau_star, 0.f);
#pragma unroll
            for (int o = 16; o; o >>= 1) psum += __shfl_xor_sync(0xFFFFFFFFu, psum, o);
            const float inv = 1.0f / (psum + 1e-10f);
            for (int j = lane; j < n; j += 32) srow[j] = fmaxf(srow[j] - tau_star, 0.f) * inv;
            for (int j = n + lane; j < tile_end; j += 32) srow[j] = 0.f;
        }
    }

    // ---- Phase 4: O = P.V (f32x2) ----
    {
        const int jg = tid >> 6;
        const int rg4 = (tid >> 4) & 3;
        const int ddg = tid & 15;

        u64 o2[4][4];
#pragma unroll
        for (int i = 0; i < 4; i++)
#pragma unroll
            for (int w = 0; w < 4; w++) o2[i][w] = 0ull;

        for (int t = 0; t < ntiles; t++) {
            const int c0 = t * COLT;
            __syncthreads();
            {
                const float4* Vg = (const float4*)(V + (size_t)c0 * DIM + hh * HD);
#pragma unroll
                for (int it = 0; it < 16; it++) {
                    int i = it * 256 + tid;
                    int j = i >> 4, dq = i & 15;
                    float4 vv = Vg[(size_t)j * 256 + dq];
                    int jq = j >> 2, jr = j & 3;
                    int p = (jq ^ dq) * 4 + jr;
                    vts[(dq * 4 + 0) * 256 + p] = vv.x;
                    vts[(dq * 4 + 1) * 256 + p] = vv.y;
                    vts[(dq * 4 + 2) * 256 + p] = vv.z;
                    vts[(dq * 4 + 3) * 256 + p] = vv.w;
                }
            }
            __syncthreads();

#pragma unroll
            for (int js = 0; js < 16; js++) {
                u64 pl[4], ph[4], vl[4], vh[4];
                const int jq = jg * 16 + js;
#pragma unroll
                for (int i = 0; i < 4; i++)
                    lds2u64(pl[i], ph[i],
                            scb + (uint32_t)(((rg4 * 4 + i) * SEQ) + c0 + jg * 64 + js * 4) * 4);
#pragma unroll
                for (int w = 0; w < 4; w++)
                    lds2u64(vl[w], vh[w],
                            kvb + (uint32_t)((ddg * 4 + w) * 64 + (jq ^ ddg)) * 16);
#pragma unroll
                for (int i = 0; i < 4; i++)
#pragma unroll
                    for (int w = 0; w < 4; w++) {
                        o2[i][w] = ffma2(pl[i], vl[w], o2[i][w]);
                        o2[i][w] = ffma2(ph[i], vh[w], o2[i][w]);
                    }
            }
        }

        // fold packed partials, reduce across the 4 j-groups through SMEM
        float oacc[4][4];
#pragma unroll
        for (int i = 0; i < 4; i++)
#pragma unroll
            for (int w = 0; w < 4; w++) {
                float2 p = upk(o2[i][w]);
                oacc[i][w] = p.x + p.y;
            }

        __syncthreads();
        float4* red4 = (float4*)kv;
#pragma unroll
        for (int i = 0; i < 4; i++) {
            red4[jg * 256 + (rg4 * 4 + i) * 16 + ddg] =
                make_float4(oacc[i][0], oacc[i][1], oacc[i][2], oacc[i][3]);
        }
        __syncthreads();
        {
            int r = tid >> 4, dq = tid & 15;
            float4 a = red4[tid], b = red4[256 + tid];
            float4 c = red4[512 + tid], d = red4[768 + tid];
            float4 s = make_float4(a.x + b.x + c.x + d.x, a.y + b.y + c.y + d.y,
                                   a.z + b.z + c.z + d.z, a.w + b.w + c.w + d.w);
            // bf16 h/m split written directly (feeds gemm_bf3 Wo projection)
            float fv[4] = {s.x, s.y, s.z, s.w};
            __nv_bfloat16 bh[4], bm[4];
#pragma unroll
            for (int q = 0; q < 4; q++) {
                bh[q] = __float2bfloat16_rn(fv[q]);
                bm[q] = __float2bfloat16_rn(fv[q] - __bfloat162float(bh[q]));
            }
            size_t idx = (size_t)(r0 + r) * DIM + hh * HD + dq * 4;
            *(__nv_bfloat162*)&AOh[idx]     = __nv_bfloat162(bh[0], bh[1]);
            *(__nv_bfloat162*)&AOh[idx + 2] = __nv_bfloat162(bh[2], bh[3]);
            *(__nv_bfloat162*)&AOm[idx]     = __nv_bfloat162(bm[0], bm[1]);
            *(__nv_bfloat162*)&AOm[idx + 2] = __nv_bfloat162(bm[2], bm[3]);
        }
    }
}

// ---------------------------------------------------------------------------
extern "C" void kernel_launch(void* const* d_in, const int* in_sizes, int n_in,
                              void* d_out, int out_size)
{
    const float* x  = (const float*)d_in[0];
    const float* Wq = (const float*)d_in[1];
    const float* Wk = (const float*)d_in[2];
    const float* Wv = (const float*)d_in[3];
    const float* Wo = (const float*)d_in[4];
    float* out = (float*)d_out;

    float *Qp, *Kp, *Vp;
    cudaGetSymbolAddress((void**)&Qp, g_Q);
    cudaGetSymbolAddress((void**)&Kp, g_K);
    cudaGetSymbolAddress((void**)&Vp, g_V);

    __nv_bfloat16 *xh, *xm, *aoh, *aom, *wvh, *wvm, *woh, *wom;
    cudaGetSymbolAddress((void**)&xh,  g_xh);  cudaGetSymbolAddress((void**)&xm,  g_xm);
    cudaGetSymbolAddress((void**)&aoh, g_aoh); cudaGetSymbolAddress((void**)&aom, g_aom);
    cudaGetSymbolAddress((void**)&wvh, g_wvh); cudaGetSymbolAddress((void**)&wvm, g_wvm);
    cudaGetSymbolAddress((void**)&woh, g_woh); cudaGetSymbolAddress((void**)&wom, g_wom);

    const size_t attn_smem = (ROWS * SEQ + ROWS * HD + 16384) * sizeof(float);
    cudaFuncSetAttribute(attn_kernel, cudaFuncAttributeMaxDynamicSharedMemorySize,
                         (int)attn_smem);
    cudaFuncSetAttribute(gemm_bf3, cudaFuncAttributeMaxDynamicSharedMemorySize, GSMEM);

    const int n4x = SEQ * DIM / 4;
    const int n4w = DIM * DIM / 4;

    // splits (flip-insensitive operands only)
    split2<<<n4x / 256, 256>>>(x,  xh,  xm,  n4x);
    split2<<<n4w / 256, 256>>>(Wv, wvh, wvm, n4w);
    split2<<<n4w / 256, 256>>>(Wo, woh, wom, n4w);

    {   // Q,K projections: fp32-faithful (entmax support is flip-sensitive)
        dim3 grid(DIM / 128, SEQ / 128, 2);
        sgemm_nt3<<<grid, 256>>>(x, Wq, Wk, Wk, Qp, Kp, Kp, DIM, DIM);
    }
    {   // V projection: bf16x3 tensor cores (errors pass linearly to output)
        dim3 grid(DIM / 128, SEQ / 128, 1);
        gemm_bf3<<<grid, 256, GSMEM>>>(xh, xm, wvh, wvm, Vp, DIM, DIM);
    }
    {   // fused entmax attention (writes bf16 h/m split directly)
        dim3 grid(SEQ / ROWS, NH);
        attn_kernel<<<grid, 256, attn_smem>>>(Qp, Kp, Vp, aoh, aom);
    }
    {   // output projection: bf16x3 tensor cores (post-entmax, flip-free)
        dim3 grid(DIM / 128, SEQ / 128, 1);
        gemm_bf3<<<grid, 256, GSMEM>>>(aoh, aom, woh, wom, out, DIM, DIM);
    }
}

// round 12
// speedup vs baseline: 2.0598x; 1.5256x over previous
#include <cuda_runtime.h>
#include <cuda_bf16.h>
#include <cstdint>
#include <cstddef>

#define SEQ 2048
#define DIM 1024
#define NH 16
#define HD 64
#define ROWS 16
#define COLT 256

// Scratch (allocation-free rule: __device__ globals)
__device__ float g_Q[SEQ * DIM];
__device__ float g_K[SEQ * DIM];
__device__ float g_V[SEQ * DIM];

__device__ __nv_bfloat16 g_xh[SEQ * DIM], g_xm[SEQ * DIM];
__device__ __nv_bfloat16 g_aoh[SEQ * DIM], g_aom[SEQ * DIM];
__device__ __nv_bfloat16 g_wvh[DIM * DIM], g_wvm[DIM * DIM];
__device__ __nv_bfloat16 g_woh[DIM * DIM], g_wom[DIM * DIM];

// ===========================================================================
// Helpers
// ===========================================================================
__device__ __forceinline__ uint32_t smem_u32(const void* p) {
    uint32_t a;
    asm("{ .reg .u64 t; cvta.to.shared.u64 t, %1; cvt.u32.u64 %0, t; }"
        : "=r"(a) : "l"(p));
    return a;
}
__device__ __forceinline__ void ldsm4(uint32_t* r, uint32_t addr) {
    asm volatile("ldmatrix.sync.aligned.m8n8.x4.shared.b16 {%0,%1,%2,%3}, [%4];"
                 : "=r"(r[0]), "=r"(r[1]), "=r"(r[2]), "=r"(r[3]) : "r"(addr));
}
__device__ __forceinline__ void mma16816(float* c, const uint32_t* a, const uint32_t* b) {
    asm volatile(
        "mma.sync.aligned.m16n8k16.row.col.f32.bf16.bf16.f32 "
        "{%0,%1,%2,%3}, {%4,%5,%6,%7}, {%8,%9}, {%0,%1,%2,%3};"
        : "+f"(c[0]), "+f"(c[1]), "+f"(c[2]), "+f"(c[3])
        : "r"(a[0]), "r"(a[1]), "r"(a[2]), "r"(a[3]), "r"(b[0]), "r"(b[1]));
}
__device__ __forceinline__ void cp16(uint32_t s, const void* g) {
    asm volatile("cp.async.ca.shared.global [%0], [%1], 16;" :: "r"(s), "l"(g));
}

// ===========================================================================
// Split fp32 -> 2x bf16 (h + m captures ~16 mantissa bits)
// ===========================================================================
__global__ __launch_bounds__(256) void split2(
    const float* __restrict__ in, __nv_bfloat16* __restrict__ h,
    __nv_bfloat16* __restrict__ m, int n4)
{
    int i = blockIdx.x * 256 + threadIdx.x;
    if (i >= n4) return;
    float4 v = ((const float4*)in)[i];
    float f[4] = {v.x, v.y, v.z, v.w};
    __nv_bfloat16 hh[4], mm[4];
#pragma unroll
    for (int j = 0; j < 4; j++) {
        hh[j] = __float2bfloat16_rn(f[j]);
        mm[j] = __float2bfloat16_rn(f[j] - __bfloat162float(hh[j]));
    }
    ((__nv_bfloat162*)h)[i * 2 + 0] = __nv_bfloat162(hh[0], hh[1]);
    ((__nv_bfloat162*)h)[i * 2 + 1] = __nv_bfloat162(hh[2], hh[3]);
    ((__nv_bfloat162*)m)[i * 2 + 0] = __nv_bfloat162(mm[0], mm[1]);
    ((__nv_bfloat162*)m)[i * 2 + 1] = __nv_bfloat162(mm[2], mm[3]);
}

// ===========================================================================
// fp32 SIMT SGEMM (fp32-faithful; feeds the entmax-sensitive score path).
// Double-buffered SMEM: one __syncthreads per K-chunk. Per-element
// accumulation order identical to R3/R7 (proven flip-safe).
// C[M,N] = A[M,K]*B[N,K]^T. blockIdx.z selects among up to 3 (B,C) pairs.
// ===========================================================================
__global__ __launch_bounds__(256, 2) void sgemm_nt3(
    const float* __restrict__ A,
    const float* __restrict__ B0, const float* __restrict__ B1, const float* __restrict__ B2,
    float* __restrict__ C0, float* __restrict__ C1, float* __restrict__ C2,
    int Kdim, int Ndim)
{
    const float* B = (blockIdx.z == 0) ? B0 : ((blockIdx.z == 1) ? B1 : B2);
    float* C = (blockIdx.z == 0) ? C0 : ((blockIdx.z == 1) ? C1 : C2);

    __shared__ __align__(16) float As[2][8][128];
    __shared__ __align__(16) float Bs[2][8][128];

    const int tid = threadIdx.x;
    const int m0 = blockIdx.y * 128;
    const int n0 = blockIdx.x * 128;
    const float* Ab = A + (size_t)m0 * Kdim;
    const float* Bb = B + (size_t)n0 * Kdim;

    const int lr = tid >> 1;
    const int lk = (tid & 1) * 4;

    const int warp = tid >> 5, lane = tid & 31;
    const int tr = (warp & 3) * 32 + (lane & 3) * 8;
    const int tc = (warp >> 2) * 64 + (lane >> 2) * 8;

    float acc[8][8];
#pragma unroll
    for (int i = 0; i < 8; i++)
#pragma unroll
        for (int j = 0; j < 8; j++) acc[i][j] = 0.f;

    const int NC = Kdim >> 3;
    for (int c = 0; c < NC; c++) {
        const int s = c & 1;
        const int k0 = c << 3;
        float4 a4 = *(const float4*)(Ab + (size_t)lr * Kdim + k0 + lk);
        float4 b4 = *(const float4*)(Bb + (size_t)lr * Kdim + k0 + lk);
        As[s][lk + 0][lr] = a4.x; As[s][lk + 1][lr] = a4.y;
        As[s][lk + 2][lr] = a4.z; As[s][lk + 3][lr] = a4.w;
        Bs[s][lk + 0][lr] = b4.x; Bs[s][lk + 1][lr] = b4.y;
        Bs[s][lk + 2][lr] = b4.z; Bs[s][lk + 3][lr] = b4.w;
        __syncthreads();
#pragma unroll
        for (int kk = 0; kk < 8; kk++) {
            float ar[8], br[8];
            *(float4*)(ar)     = *(const float4*)&As[s][kk][tr];
            *(float4*)(ar + 4) = *(const float4*)&As[s][kk][tr + 4];
            *(float4*)(br)     = *(const float4*)&Bs[s][kk][tc];
            *(float4*)(br + 4) = *(const float4*)&Bs[s][kk][tc + 4];
#pragma unroll
            for (int i = 0; i < 8; i++)
#pragma unroll
                for (int j = 0; j < 8; j++) acc[i][j] += ar[i] * br[j];
        }
        // no trailing sync: next iteration writes the other buffer; the
        // __syncthreads at the top of iteration c+1 protects buffer reuse.
    }

#pragma unroll
    for (int i = 0; i < 8; i++) {
        float* crow = C + (size_t)(m0 + tr + i) * Ndim + n0 + tc;
        *(float4*)(crow)     = make_float4(acc[i][0], acc[i][1], acc[i][2], acc[i][3]);
        *(float4*)(crow + 4) = make_float4(acc[i][4], acc[i][5], acc[i][6], acc[i][7]);
    }
}

// ===========================================================================
// bf16 3-term tensor-core GEMM: C = Ah*Bh + Am*Bh + Ah*Bm  (~2^-18 element)
// For entmax-insensitive paths only (V projection, Wo projection).
// ===========================================================================
#define GPITCH 80
#define GTILE  (128 * GPITCH)
#define GSTAGE (4 * GTILE)
#define GSMEM  (3 * GSTAGE)
#define S_AH 0
#define S_AM 1
#define S_BH 2
#define S_BM 3

__global__ __launch_bounds__(256) void gemm_bf3(
    const __nv_bfloat16* __restrict__ Ah, const __nv_bfloat16* __restrict__ Am,
    const __nv_bfloat16* __restrict__ Bh, const __nv_bfloat16* __restrict__ Bm,
    float* __restrict__ C, int Kdim, int Ndim)
{
    extern __shared__ __align__(16) char smem[];

    const int tid = threadIdx.x;
    const int lane = tid & 31, warp = tid >> 5;
    const int m0 = blockIdx.y * 128;
    const int n0 = blockIdx.x * 128;
    const int wm = (warp >> 2) * 64;
    const int wn = (warp & 3) * 32;
    const int lr = tid >> 2;
    const int lq = tid & 3;

    const uint32_t sb = smem_u32(smem);
    const uint32_t aBase = sb + (uint32_t)(wm + (lane & 15)) * GPITCH + (lane >> 4) * 16;
    const uint32_t bBase = sb + (uint32_t)(wn + ((lane >> 4) << 3) + (lane & 7)) * GPITCH
                              + ((lane >> 3) & 1) * 16;

    float acc[4][4][4];
#pragma unroll
    for (int a = 0; a < 4; a++)
#pragma unroll
        for (int b = 0; b < 4; b++)
#pragma unroll
            for (int k = 0; k < 4; k++) acc[a][b][k] = 0.f;

    const int NC = Kdim >> 5;

#define ISSUE_SUB(G, row0, sub, st, k0)                                         \
    {                                                                           \
        _Pragma("unroll")                                                       \
        for (int it = 0; it < 2; it++) {                                        \
            int r = lr + it * 64;                                               \
            cp16(sb + (st) * GSTAGE + (sub) * GTILE + r * GPITCH + lq * 16,     \
                 (const char*)(G) + ((size_t)((row0) + r) * Kdim + (k0)) * 2 + lq * 16); \
        }                                                                       \
    }
#define ISSUE(ch, st)                                                           \
    {                                                                           \
        const int k0_ = (ch) * 32;                                              \
        ISSUE_SUB(Ah, m0, S_AH, st, k0_);                                       \
        ISSUE_SUB(Am, m0, S_AM, st, k0_);                                       \
        ISSUE_SUB(Bh, n0, S_BH, st, k0_);                                       \
        ISSUE_SUB(Bm, n0, S_BM, st, k0_);                                       \
        asm volatile("cp.async.commit_group;");                                 \
    }

    ISSUE(0, 0);
    ISSUE(1, 1);

    for (int c = 0; c < NC; c++) {
        const int st = c % 3;
        if (c + 1 < NC) asm volatile("cp.async.wait_group 1;");
        else            asm volatile("cp.async.wait_group 0;");
        __syncthreads();
        if (c + 2 < NC) ISSUE(c + 2, (c + 2) % 3);

        const uint32_t sah = aBase + st * GSTAGE;
        const uint32_t sbh = bBase + st * GSTAGE + S_BH * GTILE;
#pragma unroll
        for (int ks = 0; ks < 2; ks++) {
            const uint32_t ko = ks * 32;
            uint32_t ah[4][4], am[4], bh[8], bm[8];
#pragma unroll
            for (int mb = 0; mb < 4; mb++)
                ldsm4(ah[mb], sah + S_AH * GTILE + mb * (16 * GPITCH) + ko);
            ldsm4(bh,     sbh + ko);
            ldsm4(bh + 4, sbh + 16 * GPITCH + ko);
#pragma unroll
            for (int mb = 0; mb < 4; mb++)
#pragma unroll
                for (int nb = 0; nb < 4; nb++)
                    mma16816(acc[mb][nb], ah[mb], &bh[nb * 2]);      // h*h
            ldsm4(bm,     sbh + (S_BM - S_BH) * GTILE + ko);
            ldsm4(bm + 4, sbh + (S_BM - S_BH) * GTILE + 16 * GPITCH + ko);
#pragma unroll
            for (int mb = 0; mb < 4; mb++)
#pragma unroll
                for (int nb = 0; nb < 4; nb++)
                    mma16816(acc[mb][nb], ah[mb], &bm[nb * 2]);      // h*m
#pragma unroll
            for (int mb = 0; mb < 4; mb++) {
                ldsm4(am, sah + S_AM * GTILE + mb * (16 * GPITCH) + ko);
#pragma unroll
                for (int nb = 0; nb < 4; nb++)
                    mma16816(acc[mb][nb], am, &bh[nb * 2]);          // m*h
            }
        }
    }

    const int g = lane >> 2, t = lane & 3;
#pragma unroll
    for (int mb = 0; mb < 4; mb++) {
#pragma unroll
        for (int nb = 0; nb < 4; nb++) {
            float* p0 = C + (size_t)(m0 + wm + mb * 16 + g) * Ndim + n0 + wn + nb * 8 + t * 2;
            float* p1 = p0 + 8 * Ndim;
            *(float2*)p0 = make_float2(acc[mb][nb][0], acc[mb][nb][1]);
            *(float2*)p1 = make_float2(acc[mb][nb][2], acc[mb][nb][3]);
        }
    }
#undef ISSUE
#undef ISSUE_SUB
}

// ---------------------------------------------------------------------------
// Fused causal entmax attention (R7 dense structure; phase 3 float4-vectorized;
// epilogue writes the bf16 h/m split of the attention output directly).
// ---------------------------------------------------------------------------
__global__ __launch_bounds__(256) void attn_kernel(
    const float* __restrict__ Q, const float* __restrict__ K,
    const float* __restrict__ V,
    __nv_bfloat16* __restrict__ AOh, __nv_bfloat16* __restrict__ AOm)
{
    extern __shared__ float sm[];
    float* sc = sm;                        // ROWS * SEQ
    float* qs = sm + ROWS * SEQ;           // ROWS * HD
    float* kv = qs + ROWS * HD;            // 16384 floats (tile union)
    float4* kt4 = (float4*)kv;
    float4* vt4 = (float4*)kv;
    float* vts = kv;

    const int tid = threadIdx.x;
    const int hh = blockIdx.y;             // head
    const int r0 = blockIdx.x * ROWS;
    const int n_max = r0 + ROWS;
    const int ntiles = (n_max + COLT - 1) / COLT;

    // ---- Phase 1: q rows (scale folded in) ----
    for (int i = tid; i < ROWS * HD; i += 256) {
        int r = i >> 6, d = i & 63;
        qs[r * 64 + d] = Q[(size_t)(r0 + r) * DIM + hh * HD + d] * 0.125f;
    }

    // ---- Phase 2: scores (fp32, register-blocked) ----
    {
        const int cg = tid & 63;
        const int rg = tid >> 6;
        const int cs = cg & 15;

        for (int t = 0; t < ntiles; t++) {
            const int c0 = t * COLT;
            __syncthreads();
            {
                const float4* Kg = (const float4*)(K + (size_t)c0 * DIM + hh * HD);
#pragma unroll
                for (int it = 0; it < 16; it++) {
                    int i = it * 256 + tid;
                    int c = i >> 4, dq = i & 15;
                    kt4[c * 16 + (dq ^ ((c >> 2) & 15))] = Kg[(size_t)c * 256 + dq];
                }
            }
            __syncthreads();

            float acc[4][4];
#pragma unroll
            for (int i = 0; i < 4; i++)
#pragma unroll
                for (int j = 0; j < 4; j++) acc[i][j] = 0.f;

#pragma unroll
            for (int dq = 0; dq < 16; dq++) {
                float4 q0 = *(const float4*)&qs[(rg * 4 + 0) * 64 + dq * 4];
                float4 q1 = *(const float4*)&qs[(rg * 4 + 1) * 64 + dq * 4];
                float4 q2 = *(const float4*)&qs[(rg * 4 + 2) * 64 + dq * 4];
                float4 q3 = *(const float4*)&qs[(rg * 4 + 3) * 64 + dq * 4];
                float4 k0 = kt4[(cg * 4 + 0) * 16 + (dq ^ cs)];
                float4 k1 = kt4[(cg * 4 + 1) * 16 + (dq ^ cs)];
                float4 k2 = kt4[(cg * 4 + 2) * 16 + (dq ^ cs)];
                float4 k3 = kt4[(cg * 4 + 3) * 16 + (dq ^ cs)];
#define DOT4(a, b) (a.x * b.x + a.y * b.y + a.z * b.z + a.w * b.w)
                acc[0][0] += DOT4(q0, k0); acc[0][1] += DOT4(q0, k1);
                acc[0][2] += DOT4(q0, k2); acc[0][3] += DOT4(q0, k3);
                acc[1][0] += DOT4(q1, k0); acc[1][1] += DOT4(q1, k1);
                acc[1][2] += DOT4(q1, k2); acc[1][3] += DOT4(q1, k3);
                acc[2][0] += DOT4(q2, k0); acc[2][1] += DOT4(q2, k1);
                acc[2][2] += DOT4(q2, k2); acc[2][3] += DOT4(q2, k3);
                acc[3][0] += DOT4(q3, k0); acc[3][1] += DOT4(q3, k1);
                acc[3][2] += DOT4(q3, k2); acc[3][3] += DOT4(q3, k3);
            }
#pragma unroll
            for (int i = 0; i < 4; i++) {
                *(float4*)&sc[(size_t)(rg * 4 + i) * SEQ + c0 + cg * 4] =
                    make_float4(acc[i][0], acc[i][1], acc[i][2], acc[i][3]);
            }
        }
    }
    __syncthreads();

    // ---- Phase 3: entmax per row (one warp per row, float4-vectorized) ----
    {
        const int w = tid >> 5, lane = tid & 31;
        const int tile_end = ntiles * COLT;
        for (int rr = w; rr < ROWS; rr += 8) {
            const int n = r0 + rr + 1;
            float* srow = sc + (size_t)rr * SEQ;
            const float4* srow4 = (const float4*)srow;
            const int nv = n >> 2;          // full quads
            const int ntail = nv << 2;

            // total sum
            float ssum = 0.f;
            for (int q = lane; q < nv; q += 32) {
                float4 v = srow4[q];
                ssum += (v.x + v.y) + (v.z + v.w);
            }
            for (int j = ntail + lane; j < n; j += 32) ssum += srow[j];
#pragma unroll
            for (int o = 16; o; o >>= 1) ssum += __shfl_xor_sync(0xFFFFFFFFu, ssum, o);

            // Michelot fixed point -> support size k
            int k = n;
            float tau = (ssum - 1.0f) / (float)n;
            for (int it = 0; it < SEQ; ++it) {
                float sa = 0.f; int ca = 0;
                for (int q = lane; q < nv; q += 32) {
                    float4 v = srow4[q];
                    if (v.x > tau) { sa += v.x; ca++; }
                    if (v.y > tau) { sa += v.y; ca++; }
                    if (v.z > tau) { sa += v.z; ca++; }
                    if (v.w > tau) { sa += v.w; ca++; }
                }
                for (int j = ntail + lane; j < n; j += 32) {
                    float v = srow[j];
                    if (v > tau) { sa += v; ca++; }
                }
#pragma unroll
                for (int o = 16; o; o >>= 1) {
                    sa += __shfl_xor_sync(0xFFFFFFFFu, sa, o);
                    ca += __shfl_xor_sync(0xFFFFFFFFu, ca, o);
                }
                if (ca == k) break;
                k = ca;
                tau = (sa - 1.0f) / (float)ca;
            }

            const float tau_star = (ssum - 1.0f) / (float)k;  // reference quirk: TOTAL sum

            // psum
            float psum = 0.f;
            for (int q = lane; q < nv; q += 32) {
                float4 v = srow4[q];
                psum += fmaxf(v.x - tau_star, 0.f) + fmaxf(v.y - tau_star, 0.f)
                      + fmaxf(v.z - tau_star, 0.f) + fmaxf(v.w - tau_star, 0.f);
            }
            for (int j = ntail + lane; j < n; j += 32)
                psum += fmaxf(srow[j] - tau_star, 0.f);
#pragma unroll
            for (int o = 16; o; o >>= 1) psum += __shfl_xor_sync(0xFFFFFFFFu, psum, o);
            const float inv = 1.0f / (psum + 1e-10f);

            // normalize + zero-pad
            float4* srow4w = (float4*)srow;
            for (int q = lane; q < nv; q += 32) {
                float4 v = srow4w[q];
                srow4w[q] = make_float4(fmaxf(v.x - tau_star, 0.f) * inv,
                                        fmaxf(v.y - tau_star, 0.f) * inv,
                                        fmaxf(v.z - tau_star, 0.f) * inv,
                                        fmaxf(v.w - tau_star, 0.f) * inv);
            }
            for (int j = ntail + lane; j < n; j += 32)
                srow[j] = fmaxf(srow[j] - tau_star, 0.f) * inv;
            for (int j = n + lane; j < tile_end; j += 32) srow[j] = 0.f;
        }
    }

    // ---- Phase 4: O = P.V (fp32, register-blocked) ----
    {
        const int jg = tid >> 6;
        const int rg4 = (tid >> 4) & 3;
        const int ddg = tid & 15;

        float oacc[4][4];
#pragma unroll
        for (int i = 0; i < 4; i++)
#pragma unroll
            for (int w = 0; w < 4; w++) oacc[i][w] = 0.f;

        for (int t = 0; t < ntiles; t++) {
            const int c0 = t * COLT;
            __syncthreads();
            {
                const float4* Vg = (const float4*)(V + (size_t)c0 * DIM + hh * HD);
#pragma unroll
                for (int it = 0; it < 16; it++) {
                    int i = it * 256 + tid;
                    int j = i >> 4, dq = i & 15;
                    float4 vv = Vg[(size_t)j * 256 + dq];
                    int jq = j >> 2, jr = j & 3;
                    int p = (jq ^ dq) * 4 + jr;
                    vts[(dq * 4 + 0) * 256 + p] = vv.x;
                    vts[(dq * 4 + 1) * 256 + p] = vv.y;
                    vts[(dq * 4 + 2) * 256 + p] = vv.z;
                    vts[(dq * 4 + 3) * 256 + p] = vv.w;
                }
            }
            __syncthreads();

            const float* prow0 = sc + (size_t)(rg4 * 4 + 0) * SEQ + c0 + jg * 64;
            const float* prow1 = prow0 + SEQ;
            const float* prow2 = prow1 + SEQ;
            const float* prow3 = prow2 + SEQ;
#pragma unroll
            for (int js = 0; js < 16; js++) {
                float4 p0 = *(const float4*)&prow0[js * 4];
                float4 p1 = *(const float4*)&prow1[js * 4];
                float4 p2 = *(const float4*)&prow2[js * 4];
                float4 p3 = *(const float4*)&prow3[js * 4];
                int jq = jg * 16 + js;
                float4 v0 = vt4[(ddg * 4 + 0) * 64 + (jq ^ ddg)];
                float4 v1 = vt4[(ddg * 4 + 1) * 64 + (jq ^ ddg)];
                float4 v2 = vt4[(ddg * 4 + 2) * 64 + (jq ^ ddg)];
                float4 v3 = vt4[(ddg * 4 + 3) * 64 + (jq ^ ddg)];
                oacc[0][0] += DOT4(p0, v0); oacc[0][1] += DOT4(p0, v1);
                oacc[0][2] += DOT4(p0, v2); oacc[0][3] += DOT4(p0, v3);
                oacc[1][0] += DOT4(p1, v0); oacc[1][1] += DOT4(p1, v1);
                oacc[1][2] += DOT4(p1, v2); oacc[1][3] += DOT4(p1, v3);
                oacc[2][0] += DOT4(p2, v0); oacc[2][1] += DOT4(p2, v1);
                oacc[2][2] += DOT4(p2, v2); oacc[2][3] += DOT4(p2, v3);
                oacc[3][0] += DOT4(p3, v0); oacc[3][1] += DOT4(p3, v1);
                oacc[3][2] += DOT4(p3, v2); oacc[3][3] += DOT4(p3, v3);
            }
        }

        __syncthreads();
        float4* red4 = (float4*)kv;
#pragma unroll
        for (int i = 0; i < 4; i++) {
            red4[jg * 256 + (rg4 * 4 + i) * 16 + ddg] =
                make_float4(oacc[i][0], oacc[i][1], oacc[i][2], oacc[i][3]);
        }
        __syncthreads();
        {
            int r = tid >> 4, dq = tid & 15;
            float4 a = red4[tid], b = red4[256 + tid];
            float4 c = red4[512 + tid], d = red4[768 + tid];
            float4 s = make_float4(a.x + b.x + c.x + d.x, a.y + b.y + c.y + d.y,
                                   a.z + b.z + c.z + d.z, a.w + b.w + c.w + d.w);
            // bf16 h/m split written directly (feeds gemm_bf3 Wo projection)
            float fv[4] = {s.x, s.y, s.z, s.w};
            __nv_bfloat16 bh[4], bm[4];
#pragma unroll
            for (int q = 0; q < 4; q++) {
                bh[q] = __float2bfloat16_rn(fv[q]);
                bm[q] = __float2bfloat16_rn(fv[q] - __bfloat162float(bh[q]));
            }
            size_t idx = (size_t)(r0 + r) * DIM + hh * HD + dq * 4;
            *(__nv_bfloat162*)&AOh[idx]     = __nv_bfloat162(bh[0], bh[1]);
            *(__nv_bfloat162*)&AOh[idx + 2] = __nv_bfloat162(bh[2], bh[3]);
            *(__nv_bfloat162*)&AOm[idx]     = __nv_bfloat162(bm[0], bm[1]);
            *(__nv_bfloat162*)&AOm[idx + 2] = __nv_bfloat162(bm[2], bm[3]);
        }
    }
}

// ---------------------------------------------------------------------------
extern "C" void kernel_launch(void* const* d_in, const int* in_sizes, int n_in,
                              void* d_out, int out_size)
{
    const float* x  = (const float*)d_in[0];
    const float* Wq = (const float*)d_in[1];
    const float* Wk = (const float*)d_in[2];
    const float* Wv = (const float*)d_in[3];
    const float* Wo = (const float*)d_in[4];
    float* out = (float*)d_out;

    float *Qp, *Kp, *Vp;
    cudaGetSymbolAddress((void**)&Qp, g_Q);
    cudaGetSymbolAddress((void**)&Kp, g_K);
    cudaGetSymbolAddress((void**)&Vp, g_V);

    __nv_bfloat16 *xh, *xm, *aoh, *aom, *wvh, *wvm, *woh, *wom;
    cudaGetSymbolAddress((void**)&xh,  g_xh);  cudaGetSymbolAddress((void**)&xm,  g_xm);
    cudaGetSymbolAddress((void**)&aoh, g_aoh); cudaGetSymbolAddress((void**)&aom, g_aom);
    cudaGetSymbolAddress((void**)&wvh, g_wvh); cudaGetSymbolAddress((void**)&wvm, g_wvm);
    cudaGetSymbolAddress((void**)&woh, g_woh); cudaGetSymbolAddress((void**)&wom, g_wom);

    const size_t attn_smem = (ROWS * SEQ + ROWS * HD + 16384) * sizeof(float);
    cudaFuncSetAttribute(attn_kernel, cudaFuncAttributeMaxDynamicSharedMemorySize,
                         (int)attn_smem);
    cudaFuncSetAttribute(gemm_bf3, cudaFuncAttributeMaxDynamicSharedMemorySize, GSMEM);

    const int n4x = SEQ * DIM / 4;
    const int n4w = DIM * DIM / 4;

    // splits (flip-insensitive operands only)
    split2<<<n4x / 256, 256>>>(x,  xh,  xm,  n4x);
    split2<<<n4w / 256, 256>>>(Wv, wvh, wvm, n4w);
    split2<<<n4w / 256, 256>>>(Wo, woh, wom, n4w);

    {   // Q,K projections: fp32-faithful (entmax support is flip-sensitive)
        dim3 grid(DIM / 128, SEQ / 128, 2);
        sgemm_nt3<<<grid, 256>>>(x, Wq, Wk, Wk, Qp, Kp, Kp, DIM, DIM);
    }
    {   // V projection: bf16x3 tensor cores (errors pass linearly to output)
        dim3 grid(DIM / 128, SEQ / 128, 1);
        gemm_bf3<<<grid, 256, GSMEM>>>(xh, xm, wvh, wvm, Vp, DIM, DIM);
    }
    {   // fused entmax attention (writes bf16 h/m split directly)
        dim3 grid(SEQ / ROWS, NH);
        attn_kernel<<<grid, 256, attn_smem>>>(Qp, Kp, Vp, aoh, aom);
    }
    {   // output projection: bf16x3 tensor cores (post-entmax, flip-free)
        dim3 grid(DIM / 128, SEQ / 128, 1);
        gemm_bf3<<<grid, 256, GSMEM>>>(aoh, aom, woh, wom, out, DIM, DIM);
    }
}